// round 2
// baseline (speedup 1.0000x reference)
#include <cuda_runtime.h>
#include <cuda_bf16.h>
#include <stdint.h>

// Problem constants: shape (16, 1, 320, 320) fp32, two tensors (pred, target)
#define NIMG   16
#define H      320
#define W      320
#define WPR    10              // words per row (320/32)
#define NPIX   (NIMG * H * W)  // 1,638,400 per tensor
#define NROWS  (NIMG * H)      // 5,120 per tensor
#define NWORDS (NROWS * WPR)   // 51,200 per tensor
#define SENT   0x7FFF
#define BIGF   1e12f

// Scratch (static device globals — no allocation)
__device__ uint32_t g_bits[2 * NWORDS];   // packed (v > 0.5) bits
__device__ ushort2  g_D1[2 * NPIX];       // per-pixel horiz dist: .x = to nearest TRUE, .y = to nearest FALSE
__device__ int      g_hasfg[2 * NIMG];
__device__ double   g_acc;

// ---------------------------------------------------------------------------
__global__ void k_init() {
    if (threadIdx.x == 0) g_acc = 0.0;
    if (threadIdx.x < 2 * NIMG) g_hasfg[threadIdx.x] = 0;
}

// ---------------------------------------------------------------------------
// Pack thresholded masks into bit-rows. One warp -> one 32-pixel word.
__global__ void __launch_bounds__(256) k_pack(const float* __restrict__ pred,
                                              const float* __restrict__ targ) {
    int w    = blockIdx.x * (blockDim.x >> 5) + (threadIdx.x >> 5);
    int lane = threadIdx.x & 31;
    if (w >= 2 * NWORDS) return;
    int s  = w / NWORDS;        // tensor select
    int wi = w - s * NWORDS;    // word index within tensor
    const float* src = s ? targ : pred;
    float v = src[wi * 32 + lane];
    unsigned b = __ballot_sync(0xFFFFFFFFu, v > 0.5f);
    if (lane == 0) {
        g_bits[s * NWORDS + wi] = b;
        if (b) g_hasfg[s * NIMG + wi / (H * WPR)] = 1;  // benign write race (all write 1)
    }
}

// ---------------------------------------------------------------------------
// Horizontal distance (including self) to the nearest bit of the class
// selected by pol (pol=0 -> set bits, pol=~0 -> clear bits).
__device__ __forceinline__ int nearest_dist(const uint32_t* wrow, int k, int o,
                                            uint32_t pol) {
    uint32_t c = wrow[k] ^ pol;
    int dl = SENT, dr = SENT;
    uint32_t low = c & (uint32_t)((2ull << o) - 1ull);      // bits [0..o]
    if (low) {
        dl = o - (31 - __clz(low));
    } else {
        for (int k2 = k - 1; k2 >= 0; --k2) {
            uint32_t mm = wrow[k2] ^ pol;
            if (mm) { dl = o + 32 * (k - k2) - (31 - __clz(mm)); break; }
        }
    }
    uint32_t high = c & (uint32_t)(0xFFFFFFFFull << o);     // bits [o..31]
    if (high) {
        dr = (__ffs(high) - 1) - o;
    } else {
        for (int k2 = k + 1; k2 < WPR; ++k2) {
            uint32_t mm = wrow[k2] ^ pol;
            if (mm) { dr = 32 * (k2 - k) - o + (__ffs(mm) - 1); break; }
        }
    }
    return min(min(dl, dr), SENT);
}

// ---------------------------------------------------------------------------
// Pass 1: per-pixel horizontal nearest-TRUE and nearest-FALSE distances.
// One block per row (320 threads), bit words staged in smem.
__global__ void __launch_bounds__(W) k_pass1() {
    int row = blockIdx.x;                 // [0, 2*NROWS)
    int s   = row / NROWS;
    int r   = row - s * NROWS;            // img*H + y
    __shared__ uint32_t wrow[WPR];
    int x = threadIdx.x;
    if (x < WPR) wrow[x] = g_bits[s * NWORDS + r * WPR + x];
    __syncthreads();

    int k = x >> 5, o = x & 31;
    int dT = nearest_dist(wrow, k, o, 0u);            // to nearest set bit
    int dF = nearest_dist(wrow, k, o, 0xFFFFFFFFu);   // to nearest clear bit
    g_D1[s * NPIX + r * W + x] = make_ushort2((unsigned short)dT, (unsigned short)dF);
}

// ---------------------------------------------------------------------------
// Pass 2 (vertical envelope with exact early-exit) fused with the loss.
// Query pixel of class c uses the "distance to class (not c)" component of
// every row's horizontal field.
__global__ void __launch_bounds__(256) k_loss(const float* __restrict__ pred,
                                              const float* __restrict__ targ) {
    int idx = blockIdx.x * blockDim.x + threadIdx.x;   // exactly NPIX threads
    float term = 0.f;
    if (idx < NPIX) {
        int y   = (idx / W) % H;
        int img = idx / (H * W);
        float d2v[2];
#pragma unroll
        for (int s = 0; s < 2; ++s) {
            const ushort2* D1 = g_D1 + s * NPIX;
            ushort2 own = D1[idx];
            bool isT = (own.x == 0);                  // own dT==0 <=> pixel is foreground
            int sel  = isT ? (int)own.y : (int)own.x; // distance to opposite class
            int best = sel * sel;                     // <= SENT^2 ~ 1.07e9, fits int32
            for (int dy = 1; dy * dy < best && dy < H; ++dy) {
                int dy2 = dy * dy;
                if (y - dy >= 0) {
                    ushort2 v = D1[idx - dy * W];
                    int a = isT ? (int)v.y : (int)v.x;
                    best = min(best, dy2 + a * a);
                }
                if (y + dy < H) {
                    ushort2 v = D1[idx + dy * W];
                    int a = isT ? (int)v.y : (int)v.x;
                    best = min(best, dy2 + a * a);
                }
            }
            // SENT^2 ( > any real 319^2+319^2 ) => no opposite pixel => BIG
            float f = (best >= SENT * SENT) ? BIGF : (float)best;
            if (!g_hasfg[s * NIMG + img]) f = 0.f;    // per-image no-foreground => zero field
            d2v[s] = f;
        }
        float p = pred[idx], t = targ[idx];
        float e = p - t;
        term = e * e * (d2v[0] + d2v[1]);
    }

    // block reduce -> double atomic
#pragma unroll
    for (int off = 16; off; off >>= 1)
        term += __shfl_down_sync(0xFFFFFFFFu, term, off);
    __shared__ float ws[8];
    if ((threadIdx.x & 31) == 0) ws[threadIdx.x >> 5] = term;
    __syncthreads();
    if (threadIdx.x < 8) {
        float v = ws[threadIdx.x];
#pragma unroll
        for (int off = 4; off; off >>= 1)
            v += __shfl_down_sync(0xFFu, v, off);
        if (threadIdx.x == 0) atomicAdd(&g_acc, (double)v);
    }
}

// ---------------------------------------------------------------------------
__global__ void k_final(float* __restrict__ out) {
    out[0] = (float)(g_acc / (double)NPIX);
}

// ---------------------------------------------------------------------------
extern "C" void kernel_launch(void* const* d_in, const int* in_sizes, int n_in,
                              void* d_out, int out_size) {
    const float* pred = (const float*)d_in[0];
    const float* targ = (const float*)d_in[1];
    float* out = (float*)d_out;

    k_init<<<1, 32>>>();
    k_pack<<<(2 * NWORDS + 7) / 8, 256>>>(pred, targ);   // 8 warps/block, 1 word/warp
    k_pass1<<<2 * NROWS, W>>>();
    k_loss<<<NPIX / 256, 256>>>(pred, targ);
    k_final<<<1, 1>>>(out);
}

// round 3
// speedup vs baseline: 2.2007x; 2.2007x over previous
#include <cuda_runtime.h>
#include <cuda_bf16.h>
#include <stdint.h>

// Problem constants: shape (16, 1, 320, 320) fp32, two tensors (pred, target)
#define NIMG   16
#define H      320
#define W      320
#define WPR    10              // 32-bit words per row (320/32)
#define NPIX   (NIMG * H * W)  // 1,638,400
#define NROWS  (NIMG * H)      // 5,120
#define SENT   0x7FFF
#define BIGF   1e12f
#define NB_LOSS (NPIX / 256)   // 6400 blocks in the loss kernel

// Scratch (static device globals — no allocation).
// g_D[p]: low16  = tensor0:  class<<15 | horizDistToOppositeClass
//         high16 = tensor1:  class<<15 | horizDistToOppositeClass
__device__ uint32_t     g_D[NPIX];
__device__ double       g_part[NB_LOSS];
__device__ unsigned int g_ticket = 0;   // self-resetting via atomicInc wrap

// ---------------------------------------------------------------------------
// Horizontal distance (including self) to the nearest bit of the class
// selected by pol (pol=0 -> set bits, pol=~0 -> clear bits). wrow in smem.
__device__ __forceinline__ int nearest_dist(const uint32_t* wrow, int k, int o,
                                            uint32_t pol) {
    uint32_t c = wrow[k] ^ pol;
    int dl = SENT, dr = SENT;
    uint32_t low = c & (uint32_t)((2ull << o) - 1ull);      // bits [0..o]
    if (low) {
        dl = o - (31 - __clz(low));
    } else {
        for (int k2 = k - 1; k2 >= 0; --k2) {
            uint32_t mm = wrow[k2] ^ pol;
            if (mm) { dl = o + 32 * (k - k2) - (31 - __clz(mm)); break; }
        }
    }
    uint32_t high = c & (uint32_t)(0xFFFFFFFFull << o);     // bits [o..31]
    if (high) {
        dr = (__ffs(high) - 1) - o;
    } else {
        for (int k2 = k + 1; k2 < WPR; ++k2) {
            uint32_t mm = wrow[k2] ^ pol;
            if (mm) { dr = 32 * (k2 - k) - o + (__ffs(mm) - 1); break; }
        }
    }
    return min(min(dl, dr), SENT);
}

// ---------------------------------------------------------------------------
// Kernel A: fused threshold+pack (smem ballots) + horizontal pass for BOTH
// tensors. One block per image row; 320 threads.
__global__ void __launch_bounds__(W) k_rows(const float* __restrict__ pred,
                                            const float* __restrict__ targ) {
    int r = blockIdx.x;                    // img*H + y
    int x = threadIdx.x;
    int base = r * W;

    __shared__ uint32_t wrow[2][WPR];
    int k = x >> 5, o = x & 31;

    float p = pred[base + x];
    float t = targ[base + x];
    unsigned bp = __ballot_sync(0xFFFFFFFFu, p > 0.5f);
    unsigned bt = __ballot_sync(0xFFFFFFFFu, t > 0.5f);
    if (o == 0) { wrow[0][k] = bp; wrow[1][k] = bt; }
    __syncthreads();

    uint32_t c0 = (wrow[0][k] >> o) & 1u;
    uint32_t c1 = (wrow[1][k] >> o) & 1u;
    // distance to nearest OPPOSITE-class bit (invert when own class is set)
    int d0 = nearest_dist(wrow[0], k, o, c0 ? 0xFFFFFFFFu : 0u);
    int d1 = nearest_dist(wrow[1], k, o, c1 ? 0xFFFFFFFFu : 0u);

    uint32_t v0 = (c0 << 15) | (uint32_t)d0;
    uint32_t v1 = (c1 << 15) | (uint32_t)d1;
    g_D[base + x] = v0 | (v1 << 16);
}

// ---------------------------------------------------------------------------
// Kernel B: vertical envelope (exact early-exit) + loss + full reduction.
// Last block (self-resetting ticket) reduces partials and writes the output.
__global__ void __launch_bounds__(256) k_loss(const float* __restrict__ pred,
                                              const float* __restrict__ targ,
                                              float* __restrict__ out) {
    int idx = blockIdx.x * blockDim.x + threadIdx.x;   // exactly NPIX threads
    int y = (idx / W) % H;

    uint32_t own = g_D[idx];
    uint32_t c0 = (own >> 15) & 1u;
    uint32_t c1 = (own >> 31) & 1u;
    int d0 = (int)(own & 0x7FFFu);
    int d1 = (int)((own >> 16) & 0x7FFFu);
    int best0 = d0 * d0;                  // <= SENT^2 ~ 1.07e9, fits int32
    int best1 = d1 * d1;

    int up = idx - W, dn = idx + W;
    for (int dy = 1; dy < H; ++dy) {
        int dy2 = dy * dy;
        if (dy2 >= best0 && dy2 >= best1) break;
        if (y - dy >= 0) {
            uint32_t v = g_D[up];
            int a0 = (((v >> 15) & 1u) == c0) ? (int)(v & 0x7FFFu) : 0;
            int a1 = (((v >> 31) & 1u) == c1) ? (int)((v >> 16) & 0x7FFFu) : 0;
            best0 = min(best0, dy2 + a0 * a0);
            best1 = min(best1, dy2 + a1 * a1);
        }
        if (y + dy < H) {
            uint32_t v = g_D[dn];
            int a0 = (((v >> 15) & 1u) == c0) ? (int)(v & 0x7FFFu) : 0;
            int a1 = (((v >> 31) & 1u) == c1) ? (int)((v >> 16) & 0x7FFFu) : 0;
            best0 = min(best0, dy2 + a0 * a0);
            best1 = min(best1, dy2 + a1 * a1);
        }
        up -= W; dn += W;
    }

    // Saturation: best>=SENT^2 means NO opposite-class pixel in the image.
    //   fg pixel, no bg anywhere -> field = sqrt(BIG) -> field^2 = BIG
    //   bg pixel, no fg anywhere -> reference zeroes the whole field -> 0
    float f0 = (best0 >= SENT * SENT) ? (c0 ? BIGF : 0.f) : (float)best0;
    float f1 = (best1 >= SENT * SENT) ? (c1 ? BIGF : 0.f) : (float)best1;

    float p = pred[idx], t = targ[idx];
    float e = p - t;
    float term = e * e * (f0 + f1);

    // block reduce (float) -> double partial
#pragma unroll
    for (int off = 16; off; off >>= 1)
        term += __shfl_down_sync(0xFFFFFFFFu, term, off);
    __shared__ float ws[8];
    if ((threadIdx.x & 31) == 0) ws[threadIdx.x >> 5] = term;
    __syncthreads();
    __shared__ bool isLast;
    if (threadIdx.x == 0) {
        float v = ws[0];
#pragma unroll
        for (int i = 1; i < 8; ++i) v += ws[i];
        g_part[blockIdx.x] = (double)v;
        __threadfence();
        unsigned int tk = atomicInc(&g_ticket, NB_LOSS - 1);  // wraps to 0 => self-reset
        isLast = (tk == NB_LOSS - 1);
    }
    __syncthreads();

    if (isLast) {
        // final reduction over 6400 double partials by this one block
        double acc = 0.0;
        for (int i = threadIdx.x; i < NB_LOSS; i += 256) acc += g_part[i];
#pragma unroll
        for (int off = 16; off; off >>= 1)
            acc += __shfl_down_sync(0xFFFFFFFFu, acc, off);
        __shared__ double wd[8];
        if ((threadIdx.x & 31) == 0) wd[threadIdx.x >> 5] = acc;
        __syncthreads();
        if (threadIdx.x == 0) {
            double s = wd[0];
#pragma unroll
            for (int i = 1; i < 8; ++i) s += wd[i];
            out[0] = (float)(s / (double)NPIX);
        }
    }
}

// ---------------------------------------------------------------------------
extern "C" void kernel_launch(void* const* d_in, const int* in_sizes, int n_in,
                              void* d_out, int out_size) {
    const float* pred = (const float*)d_in[0];
    const float* targ = (const float*)d_in[1];
    float* out = (float*)d_out;

    k_rows<<<NROWS, W>>>(pred, targ);
    k_loss<<<NB_LOSS, 256>>>(pred, targ, out);
}